// round 1
// baseline (speedup 1.0000x reference)
#include <cuda_runtime.h>

#define BATCH 100000
#define SEQ   28
#define IND   28
#define HID   64
#define OUTD  10
#define G3    (3*HID)   // 192
#define TPB   128

// ---- shared memory layout (float offsets) ----
#define SM_WIH  0                       // [192][28]
#define SM_WHH  (SM_WIH + G3*IND)       // [192][64]
#define SM_BRZ  (SM_WHH + G3*HID)       // combined b_ih+b_hh for r,z gates [128]
#define SM_BIN  (SM_BRZ + 2*HID)        // b_ih for n gate [64]
#define SM_BHN  (SM_BIN + HID)          // b_hh for n gate [64]
#define SM_WOUT (SM_BHN + HID)          // [10][64]
#define SM_BOUT (SM_WOUT + OUTD*HID)    // [10] (padded)
#define SM_TOTAL (SM_BOUT + 16)
// total = 18576 floats = 74304 bytes

__device__ __forceinline__ float fast_sigmoid(float x) {
    float e = __expf(-x);
    return __fdividef(1.0f, 1.0f + e);
}

__device__ __forceinline__ float fast_tanh(float x) {
    // tanh(|x|) = 1 - 2u/(1+u), u = exp(-2|x|)  (u in (0,1], no overflow/NaN)
    float ax = fabsf(x);
    float u  = __expf(-2.0f * ax);
    float t  = 1.0f - __fdividef(2.0f * u, 1.0f + u);
    return copysignf(t, x);
}

__global__ void __launch_bounds__(TPB)
gru_kernel(const float* __restrict__ x,
           const float* __restrict__ Wih,
           const float* __restrict__ Whh,
           const float* __restrict__ bih,
           const float* __restrict__ bhh,
           const float* __restrict__ Wout,
           const float* __restrict__ bout,
           float* __restrict__ out)
{
    extern __shared__ float sm[];
    const int tid = threadIdx.x;

    // ---- cooperative weight staging (coalesced; L2-resident across CTAs) ----
    for (int i = tid; i < G3*IND; i += TPB) sm[SM_WIH + i] = Wih[i];
    for (int i = tid; i < G3*HID; i += TPB) sm[SM_WHH + i] = Whh[i];
    for (int i = tid; i < 2*HID;  i += TPB) sm[SM_BRZ + i] = bih[i] + bhh[i];
    for (int i = tid; i < HID;    i += TPB) {
        sm[SM_BIN + i] = bih[2*HID + i];
        sm[SM_BHN + i] = bhh[2*HID + i];
    }
    for (int i = tid; i < OUTD*HID; i += TPB) sm[SM_WOUT + i] = Wout[i];
    for (int i = tid; i < OUTD;     i += TPB) sm[SM_BOUT + i] = bout[i];
    __syncthreads();

    const int b = blockIdx.x * TPB + tid;
    if (b >= BATCH) return;

    float h[HID];
#pragma unroll
    for (int k = 0; k < HID; k++) h[k] = 0.0f;

    const float4* __restrict__ xp =
        reinterpret_cast<const float4*>(x + (size_t)b * (SEQ * IND));

    // Per-thread staging of the step update. Written with a dynamic index on
    // purpose: forces these to local memory so the 64-float h[] array stays
    // const-indexed in registers (256 cheap LDL/STL per step vs 17664 FFMA).
    float stage_v[HID];   // (1-z)*n
    float stage_z[HID];   // z

#pragma unroll 1
    for (int t = 0; t < SEQ; t++) {
        // x_t into registers: 7x LDG.128 (aligned: b*3136 + t*112)
        float4 xv[7];
#pragma unroll
        for (int k = 0; k < 7; k++) xv[k] = xp[t * 7 + k];

#pragma unroll 1
        for (int j = 0; j < HID; j++) {
            float sr = sm[SM_BRZ + j];
            float sz = sm[SM_BRZ + HID + j];
            float si = sm[SM_BIN + j];
            float sh = sm[SM_BHN + j];

            // ---- input-projection dots (rows j, 64+j, 128+j of W_ih) ----
            const float4* wir = reinterpret_cast<const float4*>(sm + SM_WIH + j * IND);
            const float4* wiz = reinterpret_cast<const float4*>(sm + SM_WIH + (HID + j) * IND);
            const float4* win = reinterpret_cast<const float4*>(sm + SM_WIH + (2*HID + j) * IND);
#pragma unroll
            for (int k = 0; k < 7; k++) {
                float4 a = wir[k], c = wiz[k], d = win[k];
                float4 xk = xv[k];
                sr += a.x*xk.x; sr += a.y*xk.y; sr += a.z*xk.z; sr += a.w*xk.w;
                sz += c.x*xk.x; sz += c.y*xk.y; sz += c.z*xk.z; sz += c.w*xk.w;
                si += d.x*xk.x; si += d.y*xk.y; si += d.z*xk.z; si += d.w*xk.w;
            }

            // ---- hidden-projection dots (rows j, 64+j, 128+j of W_hh) ----
            const float4* whr = reinterpret_cast<const float4*>(sm + SM_WHH + j * HID);
            const float4* whz = reinterpret_cast<const float4*>(sm + SM_WHH + (HID + j) * HID);
            const float4* whn = reinterpret_cast<const float4*>(sm + SM_WHH + (2*HID + j) * HID);
#pragma unroll
            for (int k = 0; k < 16; k++) {
                float4 a = whr[k], c = whz[k], d = whn[k];
                float h0 = h[4*k], h1 = h[4*k+1], h2 = h[4*k+2], h3 = h[4*k+3];
                sr += a.x*h0; sr += a.y*h1; sr += a.z*h2; sr += a.w*h3;
                sz += c.x*h0; sz += c.y*h1; sz += c.z*h2; sz += c.w*h3;
                sh += d.x*h0; sh += d.y*h1; sh += d.z*h2; sh += d.w*h3;
            }

            float r = fast_sigmoid(sr);
            float z = fast_sigmoid(sz);
            float n = fast_tanh(si + r * sh);
            stage_v[j] = (1.0f - z) * n;
            stage_z[j] = z;
        }

        // ---- apply update: const-indexed, h stays in registers ----
#pragma unroll
        for (int k = 0; k < HID; k++)
            h[k] = stage_v[k] + stage_z[k] * h[k];
    }

    // ---- output projection ----
#pragma unroll
    for (int o = 0; o < OUTD; o++) {
        float s = sm[SM_BOUT + o];
        const float* wo = sm + SM_WOUT + o * HID;
#pragma unroll
        for (int k = 0; k < HID; k++) s += h[k] * wo[k];
        out[(size_t)b * OUTD + o] = s;
    }
}

extern "C" void kernel_launch(void* const* d_in, const int* in_sizes, int n_in,
                              void* d_out, int out_size)
{
    const float* x    = (const float*)d_in[0];
    const float* Wih  = (const float*)d_in[1];
    const float* Whh  = (const float*)d_in[2];
    const float* bih  = (const float*)d_in[3];
    const float* bhh  = (const float*)d_in[4];
    const float* Wout = (const float*)d_in[5];
    const float* bout = (const float*)d_in[6];
    float* out = (float*)d_out;

    const size_t smem_bytes = SM_TOTAL * sizeof(float);
    cudaFuncSetAttribute(gru_kernel,
                         cudaFuncAttributeMaxDynamicSharedMemorySize,
                         (int)smem_bytes);

    const int grid = (BATCH + TPB - 1) / TPB;  // 782
    gru_kernel<<<grid, TPB, smem_bytes>>>(x, Wih, Whh, bih, bhh, Wout, bout, out);
}

// round 3
// speedup vs baseline: 3.8060x; 3.8060x over previous
#include <cuda_runtime.h>
#include <stdint.h>

#define BATCH 100000
#define SEQ   28
#define IND   28
#define HID   64
#define OUTD  10
#define TPB   128
#define WARPS (TPB/32)
#define MTILE (WARPS*16)                 // 64 batch rows per CTA
#define NGRID ((BATCH + MTILE - 1)/MTILE)  // 1563

// ---------------- shared memory: weight fragments in mma lane order ----------------
struct SmemLayout {
    uint2 bx_hi[2][24][32];   // x-GEMM B frags: kt 0..1, nt 0..23 (r,z,i_n)
    uint2 bx_lo[2][24][32];
    uint2 bh_hi[4][24][32];   // h-GEMM B frags: kt 0..3, ntl 0..23 -> nt {0..15,24..31}
    uint2 bh_lo[4][24][32];
    float bias_r[HID], bias_z[HID], bias_in[HID], bias_hn[HID];
    float wout[OUTD][HID];
    float bout[OUTD];
};

// ---------------- helpers ----------------
// pack two fp32 into bf16x2: e0 -> low 16 bits, e1 -> high 16 bits
__device__ __forceinline__ uint32_t pack_bf16(float e0, float e1) {
    uint32_t r;
    asm("cvt.rn.bf16x2.f32 %0, %1, %2;" : "=r"(r) : "f"(e1), "f"(e0));
    return r;
}
__device__ __forceinline__ float bf_lo_f(uint32_t p) { return __uint_as_float(p << 16); }
__device__ __forceinline__ float bf_hi_f(uint32_t p) { return __uint_as_float(p & 0xffff0000u); }

__device__ __forceinline__ void mma16816(float* c, const uint32_t* a, uint32_t b0, uint32_t b1) {
    asm volatile(
        "mma.sync.aligned.m16n8k16.row.col.f32.bf16.bf16.f32 "
        "{%0,%1,%2,%3}, {%4,%5,%6,%7}, {%8,%9}, {%0,%1,%2,%3};"
        : "+f"(c[0]), "+f"(c[1]), "+f"(c[2]), "+f"(c[3])
        : "r"(a[0]), "r"(a[1]), "r"(a[2]), "r"(a[3]), "r"(b0), "r"(b1));
}

__device__ __forceinline__ float sigf(float v) {
    float e = __expf(-v);
    return __fdividef(1.0f, 1.0f + e);
}
__device__ __forceinline__ float tanhf_(float v) {
    float a = fabsf(v);
    float u = __expf(-2.0f * a);
    float r = 1.0f - __fdividef(2.0f * u, 1.0f + u);
    return copysignf(r, v);
}
__device__ __forceinline__ float gru_one(float rs, float zs, float is, float hs, float hold) {
    float r = sigf(rs);
    float z = sigf(zs);
    float n = tanhf_(is + r * hs);
    return (1.0f - z) * n + z * hold;
}

__global__ void __launch_bounds__(TPB, 2)
gru_mma_kernel(const float* __restrict__ x,
               const float* __restrict__ Wih,
               const float* __restrict__ Whh,
               const float* __restrict__ bih,
               const float* __restrict__ bhh,
               const float* __restrict__ Wout,
               const float* __restrict__ bout,
               float* __restrict__ out)
{
    extern __shared__ char smraw[];
    SmemLayout* sm = (SmemLayout*)smraw;
    const int tid = threadIdx.x;

    // ---- stage W_ih fragments (N rows 0..191 = r,z,i_n; K 0..31, real K<28) ----
    for (int s = tid; s < 2 * 24 * 32; s += TPB) {
        int kt = s / (24 * 32);
        int nt = (s >> 5) % 24;
        int ln = s & 31;
        int q = ln & 3, g = ln >> 2;
        int n = nt * 8 + g;              // W_ih row
        int k0 = kt * 16 + 2 * q;
        float e0 = (k0     < IND) ? Wih[n * IND + k0]     : 0.0f;
        float e1 = (k0 + 1 < IND) ? Wih[n * IND + k0 + 1] : 0.0f;
        float e2 = (k0 + 8 < IND) ? Wih[n * IND + k0 + 8] : 0.0f;
        float e3 = (k0 + 9 < IND) ? Wih[n * IND + k0 + 9] : 0.0f;
        uint32_t h0 = pack_bf16(e0, e1);
        uint32_t h1 = pack_bf16(e2, e3);
        sm->bx_hi[kt][nt][ln] = make_uint2(h0, h1);
        sm->bx_lo[kt][nt][ln] = make_uint2(
            pack_bf16(e0 - bf_lo_f(h0), e1 - bf_hi_f(h0)),
            pack_bf16(e2 - bf_lo_f(h1), e3 - bf_hi_f(h1)));
    }
    // ---- stage W_hh fragments (nt_local<16 -> r,z rows n; else h_n rows n-64) ----
    for (int s = tid; s < 4 * 24 * 32; s += TPB) {
        int kt = s / (24 * 32);
        int ntl = (s >> 5) % 24;
        int ln = s & 31;
        int q = ln & 3, g = ln >> 2;
        int ngl = (ntl < 16 ? ntl : ntl + 8) * 8 + g;   // global n: 0..127 or 192..255
        int row = (ngl < 128) ? ngl : ngl - 64;         // W_hh row
        int k0 = kt * 16 + 2 * q;
        float e0 = Whh[row * HID + k0];
        float e1 = Whh[row * HID + k0 + 1];
        float e2 = Whh[row * HID + k0 + 8];
        float e3 = Whh[row * HID + k0 + 9];
        uint32_t h0 = pack_bf16(e0, e1);
        uint32_t h1 = pack_bf16(e2, e3);
        sm->bh_hi[kt][ntl][ln] = make_uint2(h0, h1);
        sm->bh_lo[kt][ntl][ln] = make_uint2(
            pack_bf16(e0 - bf_lo_f(h0), e1 - bf_hi_f(h0)),
            pack_bf16(e2 - bf_lo_f(h1), e3 - bf_hi_f(h1)));
    }
    for (int j = tid; j < HID; j += TPB) {
        sm->bias_r[j]  = bih[j] + bhh[j];
        sm->bias_z[j]  = bih[HID + j] + bhh[HID + j];
        sm->bias_in[j] = bih[2 * HID + j];
        sm->bias_hn[j] = bhh[2 * HID + j];
    }
    for (int i = tid; i < OUTD * HID; i += TPB) ((float*)sm->wout)[i] = Wout[i];
    for (int i = tid; i < OUTD; i += TPB) sm->bout[i] = bout[i];
    __syncthreads();

    const int lane = tid & 31;
    const int wid = tid >> 5;
    const int q = lane & 3, g = lane >> 2;
    const int row0 = blockIdx.x * MTILE + wid * 16 + g;
    const int row1 = row0 + 8;
    const bool v0 = row0 < BATCH, v1 = row1 < BATCH;

    // accumulators: 32 n8-tiles x {c0..c3}; A fragments for x (2 kt) and h (4 kt)
    float acc[32][4];
    uint32_t Axh[2][4], Axl[2][4], Ahh[4][4], Ahl[4][4];
#pragma unroll
    for (int kt = 0; kt < 4; kt++)
#pragma unroll
        for (int r = 0; r < 4; r++) { Ahh[kt][r] = 0u; Ahl[kt][r] = 0u; }

    const float* xr0 = x + (size_t)(v0 ? row0 : 0) * (SEQ * IND);
    const float* xr1 = x + (size_t)(v1 ? row1 : 0) * (SEQ * IND);

#pragma unroll 1
    for (int t = 0; t < SEQ; t++) {
#pragma unroll
        for (int n = 0; n < 32; n++)
#pragma unroll
            for (int c = 0; c < 4; c++) acc[n][c] = 0.0f;

        // ---- load x_t into A fragments (hi/lo bf16 split) ----
#pragma unroll
        for (int kt = 0; kt < 2; kt++) {
#pragma unroll
            for (int half = 0; half < 2; half++) {
                int kb = kt * 16 + 2 * q + half * 8;
                float2 p0 = make_float2(0.0f, 0.0f);
                float2 p1 = make_float2(0.0f, 0.0f);
                bool kv = kb < IND;
                if (v0 && kv) p0 = *(const float2*)(xr0 + t * IND + kb);
                if (v1 && kv) p1 = *(const float2*)(xr1 + t * IND + kb);
                uint32_t H0 = pack_bf16(p0.x, p0.y);
                uint32_t H1 = pack_bf16(p1.x, p1.y);
                Axh[kt][half * 2 + 0] = H0;                     // row0
                Axh[kt][half * 2 + 1] = H1;                     // row1
                Axl[kt][half * 2 + 0] = pack_bf16(p0.x - bf_lo_f(H0), p0.y - bf_hi_f(H0));
                Axl[kt][half * 2 + 1] = pack_bf16(p1.x - bf_lo_f(H1), p1.y - bf_hi_f(H1));
            }
        }

        // ---- x GEMM: D[:,0:192] += x @ W_ih^T  (3-product bf16 split) ----
#pragma unroll
        for (int kt = 0; kt < 2; kt++) {
#pragma unroll
            for (int nt = 0; nt < 24; nt++) {
                uint2 bh = sm->bx_hi[kt][nt][lane];
                mma16816(acc[nt], Axh[kt], bh.x, bh.y);
                mma16816(acc[nt], Axl[kt], bh.x, bh.y);
                uint2 bl = sm->bx_lo[kt][nt][lane];
                mma16816(acc[nt], Axh[kt], bl.x, bl.y);
            }
        }
        // ---- h GEMM: D[:,{0:128,192:256}] += h @ W_hh^T ----
#pragma unroll
        for (int kt = 0; kt < 4; kt++) {
#pragma unroll
            for (int ntl = 0; ntl < 24; ntl++) {
                const int nt = (ntl < 16) ? ntl : ntl + 8;
                uint2 bh = sm->bh_hi[kt][ntl][lane];
                mma16816(acc[nt], Ahh[kt], bh.x, bh.y);
                mma16816(acc[nt], Ahl[kt], bh.x, bh.y);
                uint2 bl = sm->bh_lo[kt][ntl][lane];
                mma16816(acc[nt], Ahh[kt], bl.x, bl.y);
            }
        }

        // ---- epilogue: gates + h update; write h back into A frags (reg-local) ----
#pragma unroll
        for (int i = 0; i < 8; i++) {
            int j0 = i * 8 + 2 * q;
            float2 br = *(const float2*)&sm->bias_r[j0];
            float2 bz = *(const float2*)&sm->bias_z[j0];
            float2 bi = *(const float2*)&sm->bias_in[j0];
            float2 bn = *(const float2*)&sm->bias_hn[j0];
            const int kt = i >> 1;
            const int ra = (i & 1) * 2;
            float ho0 = bf_lo_f(Ahh[kt][ra])     + bf_lo_f(Ahl[kt][ra]);
            float ho1 = bf_hi_f(Ahh[kt][ra])     + bf_hi_f(Ahl[kt][ra]);
            float ho2 = bf_lo_f(Ahh[kt][ra + 1]) + bf_lo_f(Ahl[kt][ra + 1]);
            float ho3 = bf_hi_f(Ahh[kt][ra + 1]) + bf_hi_f(Ahl[kt][ra + 1]);
            float h0 = gru_one(acc[i][0] + br.x, acc[8+i][0] + bz.x, acc[16+i][0] + bi.x, acc[24+i][0] + bn.x, ho0);
            float h1 = gru_one(acc[i][1] + br.y, acc[8+i][1] + bz.y, acc[16+i][1] + bi.y, acc[24+i][1] + bn.y, ho1);
            float h2 = gru_one(acc[i][2] + br.x, acc[8+i][2] + bz.x, acc[16+i][2] + bi.x, acc[24+i][2] + bn.x, ho2);
            float h3 = gru_one(acc[i][3] + br.y, acc[8+i][3] + bz.y, acc[16+i][3] + bi.y, acc[24+i][3] + bn.y, ho3);
            uint32_t H0 = pack_bf16(h0, h1);
            uint32_t H1 = pack_bf16(h2, h3);
            Ahl[kt][ra]     = pack_bf16(h0 - bf_lo_f(H0), h1 - bf_hi_f(H0));
            Ahl[kt][ra + 1] = pack_bf16(h2 - bf_lo_f(H1), h3 - bf_hi_f(H1));
            Ahh[kt][ra]     = H0;
            Ahh[kt][ra + 1] = H1;
        }
    }

    // ---- output projection: out = hT @ W_out^T + b_out ----
    float hf[8][4];
#pragma unroll
    for (int i = 0; i < 8; i++) {
        const int kt = i >> 1, ra = (i & 1) * 2;
        hf[i][0] = bf_lo_f(Ahh[kt][ra])     + bf_lo_f(Ahl[kt][ra]);
        hf[i][1] = bf_hi_f(Ahh[kt][ra])     + bf_hi_f(Ahl[kt][ra]);
        hf[i][2] = bf_lo_f(Ahh[kt][ra + 1]) + bf_lo_f(Ahl[kt][ra + 1]);
        hf[i][3] = bf_hi_f(Ahh[kt][ra + 1]) + bf_hi_f(Ahl[kt][ra + 1]);
    }
#pragma unroll
    for (int o = 0; o < OUTD; o++) {
        float s0 = 0.0f, s1 = 0.0f;
#pragma unroll
        for (int i = 0; i < 8; i++) {
            int j0 = i * 8 + 2 * q;
            float2 w = *(const float2*)&sm->wout[o][j0];
            s0 += hf[i][0] * w.x + hf[i][1] * w.y;
            s1 += hf[i][2] * w.x + hf[i][3] * w.y;
        }
        s0 += __shfl_xor_sync(0xffffffffu, s0, 1);
        s0 += __shfl_xor_sync(0xffffffffu, s0, 2);
        s1 += __shfl_xor_sync(0xffffffffu, s1, 1);
        s1 += __shfl_xor_sync(0xffffffffu, s1, 2);
        if (q == 0) {
            float bo = sm->bout[o];
            if (v0) out[(size_t)row0 * OUTD + o] = s0 + bo;
            if (v1) out[(size_t)row1 * OUTD + o] = s1 + bo;
        }
    }
}

extern "C" void kernel_launch(void* const* d_in, const int* in_sizes, int n_in,
                              void* d_out, int out_size)
{
    const float* x    = (const float*)d_in[0];
    const float* Wih  = (const float*)d_in[1];
    const float* Whh  = (const float*)d_in[2];
    const float* bih  = (const float*)d_in[3];
    const float* bhh  = (const float*)d_in[4];
    const float* Wout = (const float*)d_in[5];
    const float* bout = (const float*)d_in[6];
    float* out = (float*)d_out;

    const int smem_bytes = (int)sizeof(SmemLayout);
    cudaFuncSetAttribute(gru_mma_kernel,
                         cudaFuncAttributeMaxDynamicSharedMemorySize, smem_bytes);

    gru_mma_kernel<<<NGRID, TPB, smem_bytes>>>(x, Wih, Whh, bih, bhh, Wout, bout, out);
}

// round 4
// speedup vs baseline: 6.4917x; 1.7056x over previous
#include <cuda_runtime.h>
#include <cuda_fp16.h>
#include <stdint.h>

#define BATCH 100000
#define SEQ   28
#define IND   28
#define HID   64
#define OUTD  10
#define TPB   64
#define WARPS (TPB/32)
#define MTILE (WARPS*16)                    // 32 batch rows per CTA
#define NGRID (BATCH/MTILE)                 // 3125 (exact)

// ---------------- shared memory: fp16 weight fragments in mma lane order ----------------
struct SmemLayout {
    uint2 bx[2][24][32];   // x-GEMM B frags (W_ih): kt 0..1, nt 0..23 (r,z,i_n)
    uint2 bh[4][24][32];   // h-GEMM B frags (W_hh): kt 0..3, ntl 0..23 -> nt {0..15,24..31}
    float bias_r[HID], bias_z[HID], bias_in[HID], bias_hn[HID];
    float wout[OUTD][HID];
    float bout[OUTD];
};

// ---------------- helpers ----------------
// pack two fp32 into f16x2: e0 -> low half, e1 -> high half
__device__ __forceinline__ uint32_t pack_f16(float e0, float e1) {
    uint32_t r;
    asm("cvt.rn.f16x2.f32 %0, %1, %2;" : "=r"(r) : "f"(e1), "f"(e0));
    return r;
}
__device__ __forceinline__ float2 unpack_f16(uint32_t p) {
    __half2 h = *reinterpret_cast<__half2*>(&p);
    return __half22float2(h);
}

__device__ __forceinline__ void mma16816(float* c, const uint32_t* a, uint32_t b0, uint32_t b1) {
    asm volatile(
        "mma.sync.aligned.m16n8k16.row.col.f32.f16.f16.f32 "
        "{%0,%1,%2,%3}, {%4,%5,%6,%7}, {%8,%9}, {%0,%1,%2,%3};"
        : "+f"(c[0]), "+f"(c[1]), "+f"(c[2]), "+f"(c[3])
        : "r"(a[0]), "r"(a[1]), "r"(a[2]), "r"(a[3]), "r"(b0), "r"(b1));
}

__device__ __forceinline__ float tanh_hw(float x) {
    float y;
    asm("tanh.approx.f32 %0, %1;" : "=f"(y) : "f"(x));
    return y;
}
__device__ __forceinline__ float sig_hw(float x) {
    return fmaf(0.5f, tanh_hw(0.5f * x), 0.5f);
}
__device__ __forceinline__ float gru_one(float rs, float zs, float is, float hs, float hold) {
    float r = sig_hw(rs);
    float z = sig_hw(zs);
    float n = tanh_hw(fmaf(r, hs, is));
    return fmaf(z, hold - n, n);           // (1-z)*n + z*h
}

__global__ void __launch_bounds__(TPB, 5)
gru_mma_kernel(const float* __restrict__ x,
               const float* __restrict__ Wih,
               const float* __restrict__ Whh,
               const float* __restrict__ bih,
               const float* __restrict__ bhh,
               const float* __restrict__ Wout,
               const float* __restrict__ bout,
               float* __restrict__ out)
{
    extern __shared__ char smraw[];
    SmemLayout* sm = (SmemLayout*)smraw;
    const int tid = threadIdx.x;

    // ---- stage W_ih fragments (N rows 0..191 = r,z,i_n; K 0..31, real K<28) ----
    for (int s = tid; s < 2 * 24 * 32; s += TPB) {
        int kt = s / (24 * 32);
        int nt = (s >> 5) % 24;
        int ln = s & 31;
        int q = ln & 3, g = ln >> 2;
        int n = nt * 8 + g;
        int k0 = kt * 16 + 2 * q;
        float e0 = (k0     < IND) ? Wih[n * IND + k0]     : 0.0f;
        float e1 = (k0 + 1 < IND) ? Wih[n * IND + k0 + 1] : 0.0f;
        float e2 = (k0 + 8 < IND) ? Wih[n * IND + k0 + 8] : 0.0f;
        float e3 = (k0 + 9 < IND) ? Wih[n * IND + k0 + 9] : 0.0f;
        sm->bx[kt][nt][ln] = make_uint2(pack_f16(e0, e1), pack_f16(e2, e3));
    }
    // ---- stage W_hh fragments (ntl<16 -> r,z rows; else h_n rows) ----
    for (int s = tid; s < 4 * 24 * 32; s += TPB) {
        int kt = s / (24 * 32);
        int ntl = (s >> 5) % 24;
        int ln = s & 31;
        int q = ln & 3, g = ln >> 2;
        int ngl = (ntl < 16 ? ntl : ntl + 8) * 8 + g;   // global n: 0..127 or 192..255
        int row = (ngl < 128) ? ngl : ngl - 64;
        int k0 = kt * 16 + 2 * q;
        float e0 = Whh[row * HID + k0];
        float e1 = Whh[row * HID + k0 + 1];
        float e2 = Whh[row * HID + k0 + 8];
        float e3 = Whh[row * HID + k0 + 9];
        sm->bh[kt][ntl][ln] = make_uint2(pack_f16(e0, e1), pack_f16(e2, e3));
    }
    for (int j = tid; j < HID; j += TPB) {
        sm->bias_r[j]  = bih[j] + bhh[j];
        sm->bias_z[j]  = bih[HID + j] + bhh[HID + j];
        sm->bias_in[j] = bih[2 * HID + j];
        sm->bias_hn[j] = bhh[2 * HID + j];
    }
    for (int i = tid; i < OUTD * HID; i += TPB) ((float*)sm->wout)[i] = Wout[i];
    for (int i = tid; i < OUTD; i += TPB) sm->bout[i] = bout[i];
    __syncthreads();

    const int lane = tid & 31;
    const int wid = tid >> 5;
    const int q = lane & 3, g = lane >> 2;
    const int row0 = blockIdx.x * MTILE + wid * 16 + g;
    const int row1 = row0 + 8;                       // always < BATCH (exact division)

    float acc[32][4];
    uint32_t Ax[2][4], Ah[4][4];
#pragma unroll
    for (int kt = 0; kt < 4; kt++)
#pragma unroll
        for (int r = 0; r < 4; r++) Ah[kt][r] = 0u;

    const float* xr0 = x + (size_t)row0 * (SEQ * IND);
    const float* xr1 = x + (size_t)row1 * (SEQ * IND);

#pragma unroll 1
    for (int t = 0; t < SEQ; t++) {
        // ---- issue x_t loads first (L2 latency hides under h-GEMM) ----
        float2 xp[2][2][2];                          // [kt][half][row01]
#pragma unroll
        for (int kt = 0; kt < 2; kt++)
#pragma unroll
            for (int half = 0; half < 2; half++) {
                int kb = kt * 16 + 2 * q + half * 8;
                if (kb < IND) {
                    xp[kt][half][0] = *(const float2*)(xr0 + t * IND + kb);
                    xp[kt][half][1] = *(const float2*)(xr1 + t * IND + kb);
                } else {
                    xp[kt][half][0] = make_float2(0.0f, 0.0f);
                    xp[kt][half][1] = make_float2(0.0f, 0.0f);
                }
            }

#pragma unroll
        for (int n = 0; n < 32; n++)
#pragma unroll
            for (int c = 0; c < 4; c++) acc[n][c] = 0.0f;

        // ---- h GEMM: D[:,{0:128,192:256}] += h @ W_hh^T ----
#pragma unroll
        for (int kt = 0; kt < 4; kt++) {
#pragma unroll
            for (int ntl = 0; ntl < 24; ntl++) {
                const int nt = (ntl < 16) ? ntl : ntl + 8;
                uint2 b = sm->bh[kt][ntl][lane];
                mma16816(acc[nt], Ah[kt], b.x, b.y);
            }
        }

        // ---- convert x to fp16 fragments ----
#pragma unroll
        for (int kt = 0; kt < 2; kt++)
#pragma unroll
            for (int half = 0; half < 2; half++) {
                Ax[kt][half * 2 + 0] = pack_f16(xp[kt][half][0].x, xp[kt][half][0].y);
                Ax[kt][half * 2 + 1] = pack_f16(xp[kt][half][1].x, xp[kt][half][1].y);
            }

        // ---- x GEMM: D[:,0:192] += x @ W_ih^T ----
#pragma unroll
        for (int kt = 0; kt < 2; kt++) {
#pragma unroll
            for (int nt = 0; nt < 24; nt++) {
                uint2 b = sm->bx[kt][nt][lane];
                mma16816(acc[nt], Ax[kt], b.x, b.y);
            }
        }

        // ---- epilogue: gates + h update; h_new written reg-locally into A frags ----
#pragma unroll
        for (int i = 0; i < 8; i++) {
            int j0 = i * 8 + 2 * q;
            float2 br = *(const float2*)&sm->bias_r[j0];
            float2 bz = *(const float2*)&sm->bias_z[j0];
            float2 bi = *(const float2*)&sm->bias_in[j0];
            float2 bn = *(const float2*)&sm->bias_hn[j0];
            const int kt = i >> 1;
            const int ra = (i & 1) * 2;
            float2 hoA = unpack_f16(Ah[kt][ra]);      // row g:   h_old[j0], h_old[j0+1]
            float2 hoB = unpack_f16(Ah[kt][ra + 1]);  // row g+8
            float h0 = gru_one(acc[i][0] + br.x, acc[8+i][0] + bz.x, acc[16+i][0] + bi.x, acc[24+i][0] + bn.x, hoA.x);
            float h1 = gru_one(acc[i][1] + br.y, acc[8+i][1] + bz.y, acc[16+i][1] + bi.y, acc[24+i][1] + bn.y, hoA.y);
            float h2 = gru_one(acc[i][2] + br.x, acc[8+i][2] + bz.x, acc[16+i][2] + bi.x, acc[24+i][2] + bn.x, hoB.x);
            float h3 = gru_one(acc[i][3] + br.y, acc[8+i][3] + bz.y, acc[16+i][3] + bi.y, acc[24+i][3] + bn.y, hoB.y);
            Ah[kt][ra]     = pack_f16(h0, h1);
            Ah[kt][ra + 1] = pack_f16(h2, h3);
        }
    }

    // ---- output projection: out = hT @ W_out^T + b_out ----
    float hf[8][4];
#pragma unroll
    for (int i = 0; i < 8; i++) {
        const int kt = i >> 1, ra = (i & 1) * 2;
        float2 a = unpack_f16(Ah[kt][ra]);
        float2 b = unpack_f16(Ah[kt][ra + 1]);
        hf[i][0] = a.x; hf[i][1] = a.y; hf[i][2] = b.x; hf[i][3] = b.y;
    }
#pragma unroll
    for (int o = 0; o < OUTD; o++) {
        float s0 = 0.0f, s1 = 0.0f;
#pragma unroll
        for (int i = 0; i < 8; i++) {
            int j0 = i * 8 + 2 * q;
            float2 w = *(const float2*)&sm->wout[o][j0];
            s0 += hf[i][0] * w.x + hf[i][1] * w.y;
            s1 += hf[i][2] * w.x + hf[i][3] * w.y;
        }
        s0 += __shfl_xor_sync(0xffffffffu, s0, 1);
        s0 += __shfl_xor_sync(0xffffffffu, s0, 2);
        s1 += __shfl_xor_sync(0xffffffffu, s1, 1);
        s1 += __shfl_xor_sync(0xffffffffu, s1, 2);
        if (q == 0) {
            float bo = sm->bout[o];
            out[(size_t)row0 * OUTD + o] = s0 + bo;
            out[(size_t)row1 * OUTD + o] = s1 + bo;
        }
    }
}

extern "C" void kernel_launch(void* const* d_in, const int* in_sizes, int n_in,
                              void* d_out, int out_size)
{
    const float* x    = (const float*)d_in[0];
    const float* Wih  = (const float*)d_in[1];
    const float* Whh  = (const float*)d_in[2];
    const float* bih  = (const float*)d_in[3];
    const float* bhh  = (const float*)d_in[4];
    const float* Wout = (const float*)d_in[5];
    const float* bout = (const float*)d_in[6];
    float* out = (float*)d_out;

    const int smem_bytes = (int)sizeof(SmemLayout);
    cudaFuncSetAttribute(gru_mma_kernel,
                         cudaFuncAttributeMaxDynamicSharedMemorySize, smem_bytes);

    gru_mma_kernel<<<NGRID, TPB, smem_bytes>>>(x, Wih, Whh, bih, bhh, Wout, bout, out);
}

// round 5
// speedup vs baseline: 9.8276x; 1.5139x over previous
#include <cuda_runtime.h>
#include <cuda_fp16.h>
#include <stdint.h>

#define BATCH 100000
#define SEQ   28
#define IND   28
#define HID   64
#define OUTD  10
#define TPB   128
#define WARPS (TPB/32)
#define MTILE (WARPS*16)                    // 64 batch rows per CTA
#define NGRID ((BATCH + MTILE - 1)/MTILE)   // 1563

// ---------------- shared memory ----------------
// B fragments stored as ldmatrix-ready 8x8 f16 matrices.
// x blocks:  [kt 0..1][pair 0..11] -> 512B = 4 matrices (b0/b1 of nt=2p, b0/b1 of nt=2p+1)
// h blocks:  [kt 0..3][pair 0..11] -> 512B likewise over ntl
// matrix row g (16B) = 8 k-contiguous f16 of weight row n
struct SmemLayout {
    __half bxm[2 * 12 * 256];   // 12288 B
    __half bhm[4 * 12 * 256];   // 24576 B
    float bias_r[HID], bias_z[HID], bias_in[HID], bias_hn[HID];
    float wout[OUTD][HID];
    float bout[OUTD];
};
#define OFF_BXM 0
#define OFF_BHM (2 * 12 * 512)

// ---------------- helpers ----------------
__device__ __forceinline__ uint32_t smem_u32(const void* p) {
    uint32_t a;
    asm("{ .reg .u64 t; cvta.to.shared.u64 t, %1; cvt.u32.u64 %0, t; }" : "=r"(a) : "l"(p));
    return a;
}
__device__ __forceinline__ uint32_t pack_f16(float e0, float e1) {
    uint32_t r;
    asm("cvt.rn.f16x2.f32 %0, %1, %2;" : "=r"(r) : "f"(e1), "f"(e0));
    return r;
}
__device__ __forceinline__ float2 unpack_f16(uint32_t p) {
    __half2 h = *reinterpret_cast<__half2*>(&p);
    return __half22float2(h);
}
__device__ __forceinline__ void ldsm_x4(uint32_t addr, uint32_t& r0, uint32_t& r1,
                                        uint32_t& r2, uint32_t& r3) {
    asm volatile("ldmatrix.sync.aligned.m8n8.x4.shared.b16 {%0,%1,%2,%3}, [%4];"
                 : "=r"(r0), "=r"(r1), "=r"(r2), "=r"(r3) : "r"(addr));
}
__device__ __forceinline__ void mma16816(float* c, const uint32_t* a, uint32_t b0, uint32_t b1) {
    asm volatile(
        "mma.sync.aligned.m16n8k16.row.col.f32.f16.f16.f32 "
        "{%0,%1,%2,%3}, {%4,%5,%6,%7}, {%8,%9}, {%0,%1,%2,%3};"
        : "+f"(c[0]), "+f"(c[1]), "+f"(c[2]), "+f"(c[3])
        : "r"(a[0]), "r"(a[1]), "r"(a[2]), "r"(a[3]), "r"(b0), "r"(b1));
}
__device__ __forceinline__ float tanh_hw(float x) {
    float y;
    asm("tanh.approx.f32 %0, %1;" : "=f"(y) : "f"(x));
    return y;
}
__device__ __forceinline__ float sig_hw(float x) {
    return fmaf(0.5f, tanh_hw(0.5f * x), 0.5f);
}
__device__ __forceinline__ float gru_one(float rs, float zs, float is, float hs, float hold) {
    float r = sig_hw(rs);
    float z = sig_hw(zs);
    float n = tanh_hw(fmaf(r, hs, is));
    return fmaf(z, hold - n, n);
}

__global__ void __launch_bounds__(TPB, 3)
gru_mma_kernel(const float* __restrict__ x,
               const float* __restrict__ Wih,
               const float* __restrict__ Whh,
               const float* __restrict__ bih,
               const float* __restrict__ bhh,
               const float* __restrict__ Wout,
               const float* __restrict__ bout,
               float* __restrict__ out)
{
    extern __shared__ char smraw[];
    SmemLayout* sm = (SmemLayout*)smraw;
    const int tid = threadIdx.x;

    // ---- stage W_ih as ldmatrix blocks ----
    // s -> blk(kt*12+pair)*256 + mat*64 + g*8 + kk ; byte offset = s*2
    for (int s = tid; s < 2 * 12 * 256; s += TPB) {
        int kk = s & 7, g = (s >> 3) & 7, mat = (s >> 6) & 3;
        int blk = s >> 8;
        int pair = blk % 12, kt = blk / 12;
        int n = pair * 16 + (mat >> 1) * 8 + g;        // 0..191
        int k = kt * 16 + (mat & 1) * 8 + kk;          // 0..31
        float v = (k < IND) ? Wih[n * IND + k] : 0.0f;
        sm->bxm[s] = __float2half_rn(v);
    }
    // ---- stage W_hh as ldmatrix blocks (ntl<16 -> r,z rows; else h_n rows) ----
    for (int s = tid; s < 4 * 12 * 256; s += TPB) {
        int kk = s & 7, g = (s >> 3) & 7, mat = (s >> 6) & 3;
        int blk = s >> 8;
        int pair = blk % 12, kt = blk / 12;
        int ntl = pair * 2 + (mat >> 1);
        int ngl = (ntl < 16 ? ntl : ntl + 8) * 8 + g;  // 0..127 or 192..255
        int row = (ngl < 128) ? ngl : ngl - 64;
        int k = kt * 16 + (mat & 1) * 8 + kk;
        sm->bhm[s] = __float2half_rn(Whh[row * HID + k]);
    }
    for (int j = tid; j < HID; j += TPB) {
        sm->bias_r[j]  = bih[j] + bhh[j];
        sm->bias_z[j]  = bih[HID + j] + bhh[HID + j];
        sm->bias_in[j] = bih[2 * HID + j];
        sm->bias_hn[j] = bhh[2 * HID + j];
    }
    for (int i = tid; i < OUTD * HID; i += TPB) ((float*)sm->wout)[i] = Wout[i];
    for (int i = tid; i < OUTD; i += TPB) sm->bout[i] = bout[i];
    __syncthreads();

    const int lane = tid & 31;
    const int wid = tid >> 5;
    const int q = lane & 3, g = lane >> 2;
    const int row0 = blockIdx.x * MTILE + wid * 16 + g;
    const int row1 = row0 + 8;
    const bool v0 = row0 < BATCH, v1 = row1 < BATCH;

    const uint32_t smb = smem_u32(smraw);
    const uint32_t bx_base = smb + OFF_BXM + (uint32_t)lane * 16u;
    const uint32_t bh_base = smb + OFF_BHM + (uint32_t)lane * 16u;

    float acc[32][4];
    uint32_t Ax[2][4], Ah[4][4];
#pragma unroll
    for (int kt = 0; kt < 4; kt++)
#pragma unroll
        for (int r = 0; r < 4; r++) Ah[kt][r] = 0u;

    const float* xr0 = x + (size_t)(v0 ? row0 : 0) * (SEQ * IND);
    const float* xr1 = x + (size_t)(v1 ? row1 : 0) * (SEQ * IND);

#pragma unroll 1
    for (int t = 0; t < SEQ; t++) {
        // ---- issue x_t loads first (L2/DRAM latency hides under h-GEMM) ----
        float2 xp[2][2][2];                          // [kt][half][row01]
#pragma unroll
        for (int kt = 0; kt < 2; kt++)
#pragma unroll
            for (int half = 0; half < 2; half++) {
                int kb = kt * 16 + 2 * q + half * 8;
                bool kv = kb < IND;
                xp[kt][half][0] = (v0 && kv) ? *(const float2*)(xr0 + t * IND + kb)
                                             : make_float2(0.0f, 0.0f);
                xp[kt][half][1] = (v1 && kv) ? *(const float2*)(xr1 + t * IND + kb)
                                             : make_float2(0.0f, 0.0f);
            }

#pragma unroll
        for (int n = 0; n < 32; n++)
#pragma unroll
            for (int c = 0; c < 4; c++) acc[n][c] = 0.0f;

        // ---- h GEMM: D[:,{0:128,192:256}] += h @ W_hh^T ----
#pragma unroll
        for (int kt = 0; kt < 4; kt++) {
#pragma unroll
            for (int p = 0; p < 12; p++) {
                uint32_t b0, b1, b2, b3;
                ldsm_x4(bh_base + (uint32_t)(kt * 12 + p) * 512u, b0, b1, b2, b3);
                const int ntl_e = 2 * p, ntl_o = 2 * p + 1;
                const int nt_e = (ntl_e < 16) ? ntl_e : ntl_e + 8;
                const int nt_o = (ntl_o < 16) ? ntl_o : ntl_o + 8;
                mma16816(acc[nt_e], Ah[kt], b0, b1);
                mma16816(acc[nt_o], Ah[kt], b2, b3);
            }
        }

        // ---- convert x to fp16 fragments ----
#pragma unroll
        for (int kt = 0; kt < 2; kt++)
#pragma unroll
            for (int half = 0; half < 2; half++) {
                Ax[kt][half * 2 + 0] = pack_f16(xp[kt][half][0].x, xp[kt][half][0].y);
                Ax[kt][half * 2 + 1] = pack_f16(xp[kt][half][1].x, xp[kt][half][1].y);
            }

        // ---- x GEMM: D[:,0:192] += x @ W_ih^T ----
#pragma unroll
        for (int kt = 0; kt < 2; kt++) {
#pragma unroll
            for (int p = 0; p < 12; p++) {
                uint32_t b0, b1, b2, b3;
                ldsm_x4(bx_base + (uint32_t)(kt * 12 + p) * 512u, b0, b1, b2, b3);
                mma16816(acc[2 * p],     Ax[kt], b0, b1);
                mma16816(acc[2 * p + 1], Ax[kt], b2, b3);
            }
        }

        // ---- epilogue: gates + h update; h_new written reg-locally into A frags ----
#pragma unroll
        for (int i = 0; i < 8; i++) {
            int j0 = i * 8 + 2 * q;
            float2 br = *(const float2*)&sm->bias_r[j0];
            float2 bz = *(const float2*)&sm->bias_z[j0];
            float2 bi = *(const float2*)&sm->bias_in[j0];
            float2 bn = *(const float2*)&sm->bias_hn[j0];
            const int kt = i >> 1;
            const int ra = (i & 1) * 2;
            float2 hoA = unpack_f16(Ah[kt][ra]);
            float2 hoB = unpack_f16(Ah[kt][ra + 1]);
            float h0 = gru_one(acc[i][0] + br.x, acc[8+i][0] + bz.x, acc[16+i][0] + bi.x, acc[24+i][0] + bn.x, hoA.x);
            float h1 = gru_one(acc[i][1] + br.y, acc[8+i][1] + bz.y, acc[16+i][1] + bi.y, acc[24+i][1] + bn.y, hoA.y);
            float h2 = gru_one(acc[i][2] + br.x, acc[8+i][2] + bz.x, acc[16+i][2] + bi.x, acc[24+i][2] + bn.x, hoB.x);
            float h3 = gru_one(acc[i][3] + br.y, acc[8+i][3] + bz.y, acc[16+i][3] + bi.y, acc[24+i][3] + bn.y, hoB.y);
            Ah[kt][ra]     = pack_f16(h0, h1);
            Ah[kt][ra + 1] = pack_f16(h2, h3);
        }
    }

    // ---- output projection: out = hT @ W_out^T + b_out ----
    float hf[8][4];
#pragma unroll
    for (int i = 0; i < 8; i++) {
        const int kt = i >> 1, ra = (i & 1) * 2;
        float2 a = unpack_f16(Ah[kt][ra]);
        float2 b = unpack_f16(Ah[kt][ra + 1]);
        hf[i][0] = a.x; hf[i][1] = a.y; hf[i][2] = b.x; hf[i][3] = b.y;
    }
#pragma unroll
    for (int o = 0; o < OUTD; o++) {
        float s0 = 0.0f, s1 = 0.0f;
#pragma unroll
        for (int i = 0; i < 8; i++) {
            int j0 = i * 8 + 2 * q;
            float2 w = *(const float2*)&sm->wout[o][j0];
            s0 += hf[i][0] * w.x + hf[i][1] * w.y;
            s1 += hf[i][2] * w.x + hf[i][3] * w.y;
        }
        s0 += __shfl_xor_sync(0xffffffffu, s0, 1);
        s0 += __shfl_xor_sync(0xffffffffu, s0, 2);
        s1 += __shfl_xor_sync(0xffffffffu, s1, 1);
        s1 += __shfl_xor_sync(0xffffffffu, s1, 2);
        if (q == 0) {
            float bo = sm->bout[o];
            if (v0) out[(size_t)row0 * OUTD + o] = s0 + bo;
            if (v1) out[(size_t)row1 * OUTD + o] = s1 + bo;
        }
    }
}

extern "C" void kernel_launch(void* const* d_in, const int* in_sizes, int n_in,
                              void* d_out, int out_size)
{
    const float* x    = (const float*)d_in[0];
    const float* Wih  = (const float*)d_in[1];
    const float* Whh  = (const float*)d_in[2];
    const float* bih  = (const float*)d_in[3];
    const float* bhh  = (const float*)d_in[4];
    const float* Wout = (const float*)d_in[5];
    const float* bout = (const float*)d_in[6];
    float* out = (float*)d_out;

    const int smem_bytes = (int)sizeof(SmemLayout);
    cudaFuncSetAttribute(gru_mma_kernel,
                         cudaFuncAttributeMaxDynamicSharedMemorySize, smem_bytes);

    gru_mma_kernel<<<NGRID, TPB, smem_bytes>>>(x, Wih, Whh, bih, bhh, Wout, bout, out);
}